// round 1
// baseline (speedup 1.0000x reference)
#include <cuda_runtime.h>

// Problem constants
#define N_TOT 8192
#define F_DIM 128
#define NF (N_TOT * F_DIM)   // 1,048,576 (n,f) pairs

// out[n,a,b,f,uv] = 0.75*(x[n,a,f,u]*y[n,b,f,v] + x[n,b,f,u]*y[n,a,f,v])
//                 - 0.5*z[n,f,uv]*(a==b)
// x: [N,3,F,2]  y: [N,3,F,2]  z: [N,F,4]  out: [N,3,3,F,4]
__global__ __launch_bounds__(256) void tp_block2_kernel(
    const float2* __restrict__ x,   // viewed as [N,3,F] float2
    const float2* __restrict__ y,   // viewed as [N,3,F] float2
    const float4* __restrict__ z,   // viewed as [N,F] float4
    float4* __restrict__ out)       // viewed as [N,3,3,F] float4
{
    int idx = blockIdx.x * blockDim.x + threadIdx.x;
    if (idx >= NF) return;
    int n = idx / F_DIM;
    int f = idx - n * F_DIM;

    // Load x[n,a,f,:] and y[n,b,f,:] for a,b in {0,1,2}
    float2 xa[3], yb[3];
    int base = (n * 3) * F_DIM + f;          // float2 index of [n,0,f]
#pragma unroll
    for (int a = 0; a < 3; a++) {
        xa[a] = x[base + a * F_DIM];
        yb[a] = y[base + a * F_DIM];
    }
    float4 zv = z[idx];                      // [n,f,:] 4 floats

    const float c1 = 0.75f;                  // NORM_112
    const float c2 = 0.5f;                   // 0.75 * 2/3

    int obase = (n * 9) * F_DIM + f;         // float4 index of out[n,0,0,f]
#pragma unroll
    for (int a = 0; a < 3; a++) {
#pragma unroll
        for (int b = 0; b < 3; b++) {
            float4 v;
            // uv order: (u,v) = (0,0),(0,1),(1,0),(1,1)
            v.x = xa[a].x * yb[b].x + xa[b].x * yb[a].x;
            v.y = xa[a].x * yb[b].y + xa[b].x * yb[a].y;
            v.z = xa[a].y * yb[b].x + xa[b].y * yb[a].x;
            v.w = xa[a].y * yb[b].y + xa[b].y * yb[a].y;
            v.x *= c1; v.y *= c1; v.z *= c1; v.w *= c1;
            if (a == b) {
                v.x -= c2 * zv.x;
                v.y -= c2 * zv.y;
                v.z -= c2 * zv.z;
                v.w -= c2 * zv.w;
            }
            out[obase + (a * 3 + b) * F_DIM] = v;
        }
    }
}

extern "C" void kernel_launch(void* const* d_in, const int* in_sizes, int n_in,
                              void* d_out, int out_size) {
    const float2* x = (const float2*)d_in[0];
    const float2* y = (const float2*)d_in[1];
    const float4* z = (const float4*)d_in[2];
    // d_in[3] is eye (identity) — value known, not needed.
    float4* out = (float4*)d_out;

    const int threads = 256;
    const int blocks = (NF + threads - 1) / threads;
    tp_block2_kernel<<<blocks, threads>>>(x, y, z, out);
}

// round 2
// speedup vs baseline: 1.0086x; 1.0086x over previous
#include <cuda_runtime.h>

// Problem constants
#define N_TOT 8192
#define F_DIM 128
#define NF (N_TOT * F_DIM)   // 1,048,576 (n,f) pairs

// out[n,a,b,f,uv] = 0.75*(x[n,a,f,u]*y[n,b,f,v] + x[n,b,f,u]*y[n,a,f,v])
//                 - 0.5*z[n,f,uv]*(a==b)
// x: [N,3,F,2]  y: [N,3,F,2]  z: [N,F,4]  out: [N,3,3,F,4]
//
// Pure streaming kernel: every byte of input/output is touched exactly once,
// so all loads are evict-first (__ldcs) and all stores streaming (__stcs) to
// minimize L2 residency pressure from the 151 MB write stream.
__global__ __launch_bounds__(256) void tp_block2_kernel(
    const float2* __restrict__ x,   // viewed as [N,3,F] float2
    const float2* __restrict__ y,   // viewed as [N,3,F] float2
    const float4* __restrict__ z,   // viewed as [N,F] float4
    float4* __restrict__ out)       // viewed as [N,3,3,F] float4
{
    int idx = blockIdx.x * blockDim.x + threadIdx.x;
    if (idx >= NF) return;
    int n = idx / F_DIM;
    int f = idx - n * F_DIM;

    // Front-batch all 7 loads for max MLP.
    int base = (n * 3) * F_DIM + f;          // float2 index of [n,0,f]
    float2 xa0 = __ldcs(&x[base]);
    float2 xa1 = __ldcs(&x[base + F_DIM]);
    float2 xa2 = __ldcs(&x[base + 2 * F_DIM]);
    float2 yb0 = __ldcs(&y[base]);
    float2 yb1 = __ldcs(&y[base + F_DIM]);
    float2 yb2 = __ldcs(&y[base + 2 * F_DIM]);
    float4 zv  = __ldcs(&z[idx]);

    float2 xa[3] = {xa0, xa1, xa2};
    float2 yb[3] = {yb0, yb1, yb2};

    const float c1 = 0.75f;                  // NORM_112
    const float c2 = 0.5f;                   // 0.75 * 2/3

    // Pre-scale z once (diagonal term).
    float4 zc;
    zc.x = c2 * zv.x; zc.y = c2 * zv.y; zc.z = c2 * zv.z; zc.w = c2 * zv.w;

    int obase = (n * 9) * F_DIM + f;         // float4 index of out[n,0,0,f]
#pragma unroll
    for (int a = 0; a < 3; a++) {
#pragma unroll
        for (int b = 0; b < 3; b++) {
            float4 v;
            // uv order: (u,v) = (0,0),(0,1),(1,0),(1,1)
            v.x = c1 * (xa[a].x * yb[b].x + xa[b].x * yb[a].x);
            v.y = c1 * (xa[a].x * yb[b].y + xa[b].x * yb[a].y);
            v.z = c1 * (xa[a].y * yb[b].x + xa[b].y * yb[a].x);
            v.w = c1 * (xa[a].y * yb[b].y + xa[b].y * yb[a].y);
            if (a == b) {
                v.x -= zc.x;
                v.y -= zc.y;
                v.z -= zc.z;
                v.w -= zc.w;
            }
            __stcs(&out[obase + (a * 3 + b) * F_DIM], v);
        }
    }
}

extern "C" void kernel_launch(void* const* d_in, const int* in_sizes, int n_in,
                              void* d_out, int out_size) {
    const float2* x = (const float2*)d_in[0];
    const float2* y = (const float2*)d_in[1];
    const float4* z = (const float4*)d_in[2];
    // d_in[3] is eye (identity) — value known, not needed.
    float4* out = (float4*)d_out;

    const int threads = 256;
    const int blocks = (NF + threads - 1) / threads;
    tp_block2_kernel<<<blocks, threads>>>(x, y, z, out);
}